// round 8
// baseline (speedup 1.0000x reference)
#include <cuda_runtime.h>

#define N_BATCH 64
#define L_LEN   512
#define F_LEN   2048

#define QPB     32                      // queries per block (one warp-lane each)
#define NSLICE  8                       // F split across 8 warps
#define SLICE   (F_LEN / NSLICE)        // 256 candidates per warp
#define NBLOCKS ((N_BATCH * L_LEN) / QPB)  // 1024
#define BPN     (L_LEN / QPB)           // 16 blocks per batch row

__device__ float g_part[NBLOCKS];       // per-block max-over-queries of NN dist
__device__ int   g_done = 0;            // last block resets it -> always 0 at replay start

// Chebyshev eval in 3 issue slots: packed f32x2 add computes (dx,dy) in one op
// (B stored pre-negated), then one FMNMX with |.| modifiers.
__device__ __forceinline__ float cheb(unsigned long long ap, unsigned long long bp) {
    float dx, dy;
    asm("{\n\t"
        ".reg .b64 d;\n\t"
        "add.rn.f32x2 d, %2, %3;\n\t"
        "mov.b64 {%0, %1}, d;\n\t"
        "}" : "=f"(dx), "=f"(dy) : "l"(ap), "l"(bp));
    return fmaxf(fabsf(dx), fabsf(dy));
}

__global__ __launch_bounds__(256) void fused_kernel(const float* __restrict__ A,
                                                    const float* __restrict__ B,
                                                    float* __restrict__ out) {
    __shared__ ulonglong2 sB[F_LEN / 2];       // interleaved (-bx,-by), 2 cands/entry: 16KB
    __shared__ float sPart[NSLICE * QPB];      // per (slice, query) partial mins
    __shared__ int   sLast;

    const int tid  = threadIdx.x;
    const int w    = tid >> 5;     // slice id (= warp id)
    const int lane = tid & 31;     // query id within block

    // Cooperative fill: negate B and interleave channels -> packed operand pairs.
    #pragma unroll
    for (int i = tid; i < F_LEN / 4; i += 256) {
        const float4 x = reinterpret_cast<const float4*>(B)[i];            // B[0][f]
        const float4 y = reinterpret_cast<const float4*>(B + F_LEN)[i];    // B[1][f]
        float2* dst = reinterpret_cast<float2*>(sB) + i * 4;
        dst[0] = make_float2(-x.x, -y.x);
        dst[1] = make_float2(-x.y, -y.y);
        dst[2] = make_float2(-x.z, -y.z);
        dst[3] = make_float2(-x.w, -y.w);
    }

    // This thread's query point, packed once into a b64 pair.
    const int q = blockIdx.x * QPB + lane;
    const float2 a = reinterpret_cast<const float2*>(A)[q];
    unsigned long long ap;
    asm("mov.b64 %0, {%1, %2};" : "=l"(ap) : "f"(a.x), "f"(a.y));

    __syncthreads();

    // Scan this warp's 256-candidate slice. All lanes read the SAME smem
    // address -> broadcast, conflict-free. 4 independent accumulators for ILP.
    const ulonglong2* __restrict__ p = sB + w * (SLICE / 2);
    float m0 = 1e30f, m1 = 1e30f, m2 = 1e30f, m3 = 1e30f;

    #pragma unroll 4
    for (int i = 0; i < SLICE / 8; ++i) {      // 8 candidates per iteration
        const ulonglong2 v0 = p[i * 4 + 0];
        const ulonglong2 v1 = p[i * 4 + 1];
        const ulonglong2 v2 = p[i * 4 + 2];
        const ulonglong2 v3 = p[i * 4 + 3];
        const float t0 = cheb(ap, v0.x), t1 = cheb(ap, v0.y);
        const float t2 = cheb(ap, v1.x), t3 = cheb(ap, v1.y);
        const float t4 = cheb(ap, v2.x), t5 = cheb(ap, v2.y);
        const float t6 = cheb(ap, v3.x), t7 = cheb(ap, v3.y);
        m0 = fminf(m0, fminf(t0, t1));
        m1 = fminf(m1, fminf(t2, t3));
        m2 = fminf(m2, fminf(t4, t5));
        m3 = fminf(m3, fminf(t6, t7));
    }

    sPart[w * QPB + lane] = fminf(fminf(m0, m1), fminf(m2, m3));
    __syncthreads();

    if (w == 0) {
        // min over the 8 slices -> full min over f for query `lane`
        float b = sPart[lane];
        #pragma unroll
        for (int s = 1; s < NSLICE; ++s)
            b = fminf(b, sPart[s * QPB + lane]);           // conflict-free (bank = lane)
        // max over the block's 32 queries (all same n)
        #pragma unroll
        for (int off = 16; off; off >>= 1)
            b = fmaxf(b, __shfl_xor_sync(0xffffffffu, b, off));
        if (lane == 0)
            g_part[blockIdx.x] = b;
    }

    // Fused finish: last block to arrive reduces per-n partials + sigmoids.
    __threadfence();   // release g_part store (tid 0 wrote it; fence-before-atomic)
    if (tid == 0)
        sLast = (atomicAdd(&g_done, 1) == NBLOCKS - 1);
    __syncthreads();

    if (sLast) {
        if (tid < N_BATCH) {
            __threadfence();           // acquire all blocks' g_part stores
            float mx = 0.0f;           // distances are >= 0
            #pragma unroll
            for (int k = 0; k < BPN; ++k)
                mx = fmaxf(mx, __ldcg(&g_part[tid * BPN + k]));   // bypass L1
            const float s1 = 1.0f / (1.0f + expf(-10.0f * mx));
            const float s2 = 1.0f / (1.0f + expf( 10.0f * mx));
            out[tid] = s1 * s2;
        }
        if (tid == 0)
            g_done = 0;                // leave counter clean for the next replay
    }
}

extern "C" void kernel_launch(void* const* d_in, const int* in_sizes, int n_in,
                              void* d_out, int out_size) {
    const float* A = (const float*)d_in[0];   // (64, 512, 2) fp32
    const float* B = (const float*)d_in[1];   // (1, 2, 2048) fp32
    float* out = (float*)d_out;               // (64, 1) fp32

    fused_kernel<<<NBLOCKS, 256>>>(A, B, out);
}

// round 9
// speedup vs baseline: 1.0171x; 1.0171x over previous
#include <cuda_runtime.h>

#define N_BATCH 64
#define L_LEN   512
#define F_LEN   2048

#define QPB     32                      // queries per block (one warp-lane each)
#define NSLICE  8                       // F split across 8 warps
#define SLICE   (F_LEN / NSLICE)        // 256 candidates per warp
#define NBLOCKS ((N_BATCH * L_LEN) / QPB)  // 1024
#define BPN     (L_LEN / QPB)           // 16 blocks per batch row

__device__ float g_part[NBLOCKS];       // per-block max-over-queries of NN dist
__device__ int   g_done = 0;            // last block resets it -> always 0 at replay start

// Chebyshev eval in 3 issue slots: packed f32x2 add computes (dx,dy) in one op
// (B stored pre-negated), then one FMNMX with |.| modifiers.
__device__ __forceinline__ float cheb(unsigned long long ap, unsigned long long bp) {
    float dx, dy;
    asm("{\n\t"
        ".reg .b64 d;\n\t"
        "add.rn.f32x2 d, %2, %3;\n\t"
        "mov.b64 {%0, %1}, d;\n\t"
        "}" : "=f"(dx), "=f"(dy) : "l"(ap), "l"(bp));
    return fmaxf(fabsf(dx), fabsf(dy));
}

__global__ __launch_bounds__(256) void fused_kernel(const float* __restrict__ A,
                                                    const float* __restrict__ B,
                                                    float* __restrict__ out) {
    __shared__ ulonglong2 sB[F_LEN / 2];       // interleaved (-bx,-by), 2 cands/entry: 16KB
    __shared__ float sPart[NSLICE * QPB];      // per (slice, query) partial mins
    __shared__ int   sLast;

    const int tid  = threadIdx.x;
    const int w    = tid >> 5;     // slice id (= warp id)
    const int lane = tid & 31;     // query id within block

    // Cooperative fill: negate B and interleave channels -> packed operand pairs.
    #pragma unroll
    for (int i = tid; i < F_LEN / 4; i += 256) {
        const float4 x = reinterpret_cast<const float4*>(B)[i];            // B[0][f]
        const float4 y = reinterpret_cast<const float4*>(B + F_LEN)[i];    // B[1][f]
        float2* dst = reinterpret_cast<float2*>(sB) + i * 4;
        dst[0] = make_float2(-x.x, -y.x);
        dst[1] = make_float2(-x.y, -y.y);
        dst[2] = make_float2(-x.z, -y.z);
        dst[3] = make_float2(-x.w, -y.w);
    }

    // This thread's query point, packed once into a b64 pair.
    const int q = blockIdx.x * QPB + lane;
    const float2 a = reinterpret_cast<const float2*>(A)[q];
    unsigned long long ap;
    asm("mov.b64 %0, {%1, %2};" : "=l"(ap) : "f"(a.x), "f"(a.y));

    __syncthreads();

    // Scan this warp's 256-candidate slice. All lanes read the SAME smem
    // address -> broadcast, conflict-free. 4 independent accumulators for ILP.
    const ulonglong2* __restrict__ p = sB + w * (SLICE / 2);
    float m0 = 1e30f, m1 = 1e30f, m2 = 1e30f, m3 = 1e30f;

    #pragma unroll 4
    for (int i = 0; i < SLICE / 8; ++i) {      // 8 candidates per iteration
        const ulonglong2 v0 = p[i * 4 + 0];
        const ulonglong2 v1 = p[i * 4 + 1];
        const ulonglong2 v2 = p[i * 4 + 2];
        const ulonglong2 v3 = p[i * 4 + 3];
        const float t0 = cheb(ap, v0.x), t1 = cheb(ap, v0.y);
        const float t2 = cheb(ap, v1.x), t3 = cheb(ap, v1.y);
        const float t4 = cheb(ap, v2.x), t5 = cheb(ap, v2.y);
        const float t6 = cheb(ap, v3.x), t7 = cheb(ap, v3.y);
        m0 = fminf(m0, fminf(t0, t1));
        m1 = fminf(m1, fminf(t2, t3));
        m2 = fminf(m2, fminf(t4, t5));
        m3 = fminf(m3, fminf(t6, t7));
    }

    sPart[w * QPB + lane] = fminf(fminf(m0, m1), fminf(m2, m3));
    __syncthreads();

    if (w == 0) {
        // min over the 8 slices -> full min over f for query `lane`
        float b = sPart[lane];
        #pragma unroll
        for (int s = 1; s < NSLICE; ++s)
            b = fminf(b, sPart[s * QPB + lane]);           // conflict-free (bank = lane)
        // max over the block's 32 queries (all same n)
        #pragma unroll
        for (int off = 16; off; off >>= 1)
            b = fmaxf(b, __shfl_xor_sync(0xffffffffu, b, off));
        if (lane == 0)
            g_part[blockIdx.x] = b;
    }

    // Fused finish: last block to arrive reduces per-n partials + sigmoids.
    __threadfence();   // release g_part store (tid 0 wrote it; fence-before-atomic)
    if (tid == 0)
        sLast = (atomicAdd(&g_done, 1) == NBLOCKS - 1);
    __syncthreads();

    if (sLast) {
        if (tid < N_BATCH) {
            __threadfence();           // acquire all blocks' g_part stores
            float mx = 0.0f;           // distances are >= 0
            #pragma unroll
            for (int k = 0; k < BPN; ++k)
                mx = fmaxf(mx, __ldcg(&g_part[tid * BPN + k]));   // bypass L1
            const float s1 = 1.0f / (1.0f + expf(-10.0f * mx));
            const float s2 = 1.0f / (1.0f + expf( 10.0f * mx));
            out[tid] = s1 * s2;
        }
        if (tid == 0)
            g_done = 0;                // leave counter clean for the next replay
    }
}

extern "C" void kernel_launch(void* const* d_in, const int* in_sizes, int n_in,
                              void* d_out, int out_size) {
    const float* A = (const float*)d_in[0];   // (64, 512, 2) fp32
    const float* B = (const float*)d_in[1];   // (1, 2, 2048) fp32
    float* out = (float*)d_out;               // (64, 1) fp32

    fused_kernel<<<NBLOCKS, 256>>>(A, B, out);
}